// round 9
// baseline (speedup 1.0000x reference)
#include <cuda_runtime.h>
#include <cstdint>

// Problem constants
#define B_  8
#define S_  1024
#define D_  1024
#define H_  16
#define DH_ 64

// Scratch buffers (allocation-free rule: __device__ globals)
__device__ float g_qkv[(size_t)B_ * S_ * 3 * D_];   // [B, S, 3D] tf32-rounded
__device__ float g_attn[(size_t)B_ * S_ * D_];      // [B, S, D]  tf32-rounded
__device__ float g_x[(size_t)B_ * S_ * D_];         // tf32-rounded copy of x
__device__ float g_wqkv[(size_t)D_ * 3 * D_];       // tf32-rounded W_qkv
__device__ float g_wout[(size_t)D_ * D_];           // tf32-rounded W_out

// ---------------------------------------------------------------------------
// TF32 helpers
// ---------------------------------------------------------------------------
__device__ __forceinline__ uint32_t f2tf32(float f) {
    uint32_t r;
    asm("cvt.rna.tf32.f32 %0, %1;" : "=r"(r) : "f"(f));
    return r;
}
__device__ __forceinline__ float tf32r(float f) {
    return __uint_as_float(f2tf32(f));
}

__device__ __forceinline__ void mma_tf32(
    float& d0, float& d1, float& d2, float& d3,
    uint32_t a0, uint32_t a1, uint32_t a2, uint32_t a3,
    uint32_t b0, uint32_t b1)
{
    asm volatile(
        "mma.sync.aligned.m16n8k8.row.col.f32.tf32.tf32.f32 "
        "{%0,%1,%2,%3}, {%4,%5,%6,%7}, {%8,%9}, {%0,%1,%2,%3};"
        : "+f"(d0), "+f"(d1), "+f"(d2), "+f"(d3)
        : "r"(a0), "r"(a1), "r"(a2), "r"(a3), "r"(b0), "r"(b1));
}

__device__ __forceinline__ void cp_async16(uint32_t s, const void* g) {
    asm volatile("cp.async.cg.shared.global [%0], [%1], 16;" :: "r"(s), "l"(g));
}
__device__ __forceinline__ uint32_t smem_u32(const void* p) {
    return (uint32_t)__cvta_generic_to_shared(p);
}

// ---------------------------------------------------------------------------
// Elementwise tf32 pre-round (float4 grid-stride)
// ---------------------------------------------------------------------------
__global__ void round_tf32_kernel(const float* __restrict__ in,
                                  float* __restrict__ out, int n4)
{
    int i = blockIdx.x * blockDim.x + threadIdx.x;
    if (i < n4) {
        float4 v = reinterpret_cast<const float4*>(in)[i];
        v.x = tf32r(v.x); v.y = tf32r(v.y);
        v.z = tf32r(v.z); v.w = tf32r(v.w);
        reinterpret_cast<float4*>(out)[i] = v;
    }
}

// ---------------------------------------------------------------------------
// TF32 GEMM (unchanged from R8): block 128x128, 4 warps (2x2), warp tile
// 64x64, BK=32, 3-stage cp.async pipeline + register double-buffered frags.
// ---------------------------------------------------------------------------
#define AS_STRIDE 36
#define BS_STRIDE 136
#define A_TILE_F (128 * AS_STRIDE)
#define B_TILE_F (32 * BS_STRIDE)
#define BUF_F    (A_TILE_F + B_TILE_F)
#define SMEM_BYTES (3 * BUF_F * 4)

template<bool ROUND_OUT>
__global__ __launch_bounds__(128, 2) void gemm_tf32_kernel(
    const float* __restrict__ A, const float* __restrict__ W,
    const float* __restrict__ bias, float* __restrict__ C,
    int M, int N, int K)
{
    extern __shared__ float sm[];

    const int tid  = threadIdx.x;
    const int lane = tid & 31;
    const int warp = tid >> 5;
    const int wm   = warp & 1;
    const int wn   = warp >> 1;
    const int mBase = blockIdx.y * 128;
    const int nBase = blockIdx.x * 128;
    const int g  = lane >> 2;
    const int t  = lane & 3;

    float acc[4][8][4];
    #pragma unroll
    for (int mt = 0; mt < 4; ++mt)
        #pragma unroll
        for (int nt = 0; nt < 8; ++nt)
            #pragma unroll
            for (int f = 0; f < 4; ++f) acc[mt][nt][f] = 0.0f;

    auto loadTile = [&](int buf, int k0) {
        float* As = sm + buf * BUF_F;
        float* Bs = As + A_TILE_F;
        #pragma unroll
        for (int j = 0; j < 8; ++j) {
            int idx = tid + j * 128;
            int r = idx >> 3, c4 = idx & 7;
            cp_async16(smem_u32(As + r * AS_STRIDE + c4 * 4),
                       &A[(size_t)(mBase + r) * K + k0 + c4 * 4]);
        }
        #pragma unroll
        for (int j = 0; j < 8; ++j) {
            int idx = tid + j * 128;
            int r = idx >> 5, c4 = idx & 31;
            cp_async16(smem_u32(Bs + r * BS_STRIDE + c4 * 4),
                       &W[(size_t)(k0 + r) * N + nBase + c4 * 4]);
        }
        asm volatile("cp.async.commit_group;");
    };

    uint32_t af[2][4][4];
    uint32_t bf[2][8][2];

    const int aRow = wm * 64;
    const int bCol = wn * 64;

    auto loadFragsA = [&](int pb, const uint32_t* As, int kc) {
        #pragma unroll
        for (int mt = 0; mt < 4; ++mt) {
            int r = aRow + mt * 16 + g;
            af[pb][mt][0] = As[(r    ) * AS_STRIDE + kc + t    ];
            af[pb][mt][1] = As[(r + 8) * AS_STRIDE + kc + t    ];
            af[pb][mt][2] = As[(r    ) * AS_STRIDE + kc + t + 4];
            af[pb][mt][3] = As[(r + 8) * AS_STRIDE + kc + t + 4];
        }
    };
    auto loadFragsB = [&](int pb, const uint32_t* Bs, int kc) {
        #pragma unroll
        for (int nt = 0; nt < 8; ++nt) {
            int n = bCol + nt * 8 + g;
            bf[pb][nt][0] = Bs[(kc + t    ) * BS_STRIDE + n];
            bf[pb][nt][1] = Bs[(kc + t + 4) * BS_STRIDE + n];
        }
    };

    const int nIter = K / 32;
    loadTile(0, 0);
    loadTile(1, 32);

    for (int it = 0; it < nIter; ++it) {
        if (it + 1 < nIter) {
            asm volatile("cp.async.wait_group 1;");
        } else {
            asm volatile("cp.async.wait_group 0;");
        }
        __syncthreads();

        if (it + 2 < nIter)
            loadTile((it + 2) % 3, (it + 2) * 32);

        const uint32_t* As = reinterpret_cast<const uint32_t*>(sm + (it % 3) * BUF_F);
        const uint32_t* Bs = As + A_TILE_F;

        loadFragsA(0, As, 0);
        loadFragsB(0, Bs, 0);

        #pragma unroll
        for (int kk = 0; kk < 4; ++kk) {
            const int cur = kk & 1;
            const int nxt = cur ^ 1;
            if (kk < 3) {
                loadFragsA(nxt, As, (kk + 1) * 8);
                loadFragsB(nxt, Bs, (kk + 1) * 8);
            }
            #pragma unroll
            for (int mt = 0; mt < 4; ++mt)
                #pragma unroll
                for (int nt = 0; nt < 8; ++nt)
                    mma_tf32(acc[mt][nt][0], acc[mt][nt][1],
                             acc[mt][nt][2], acc[mt][nt][3],
                             af[cur][mt][0], af[cur][mt][1],
                             af[cur][mt][2], af[cur][mt][3],
                             bf[cur][nt][0], bf[cur][nt][1]);
        }
    }

    #pragma unroll
    for (int mt = 0; mt < 4; ++mt) {
        int r0 = mBase + wm * 64 + mt * 16 + g;
        int r1 = r0 + 8;
        #pragma unroll
        for (int nt = 0; nt < 8; ++nt) {
            int col = nBase + wn * 64 + nt * 8 + t * 2;
            float2 bv = *reinterpret_cast<const float2*>(&bias[col]);
            float2 v0, v1;
            v0.x = acc[mt][nt][0] + bv.x;
            v0.y = acc[mt][nt][1] + bv.y;
            v1.x = acc[mt][nt][2] + bv.x;
            v1.y = acc[mt][nt][3] + bv.y;
            if (ROUND_OUT) {
                v0.x = tf32r(v0.x); v0.y = tf32r(v0.y);
                v1.x = tf32r(v1.x); v1.y = tf32r(v1.y);
            }
            *reinterpret_cast<float2*>(&C[(size_t)r0 * N + col]) = v0;
            *reinterpret_cast<float2*>(&C[(size_t)r1 * N + col]) = v1;
        }
    }
}

// ---------------------------------------------------------------------------
// Tensor-core FlashAttention v2 (tf32, causal) — occupancy-oriented:
// q-tile 64 rows, 128 threads = 4 warps, warp tile 16x64, smem 52KB,
// target 4 CTAs/SM (16 warps = 4/SMSP) to hide LDS/MUFU/shuffle latency.
// Per-row math identical to R5 kernel (same tiles, same order).
// grid = (16, B*H), q0 = (15-bx)*64 (heavy tiles first).
// ---------------------------------------------------------------------------
#define QP_STRIDE 68
#define K_STRIDE  68
#define V_STRIDE  72
#define QP_F (64 * QP_STRIDE)           // 4352 floats
#define K_F  (64 * K_STRIDE)            // 4352
#define V_F  (64 * V_STRIDE)            // 4608
#define ATT_SMEM_BYTES ((QP_F + K_F + V_F) * 4)   // 53248 B

__global__ __launch_bounds__(128, 4) void attention_tc_kernel(
    const float* __restrict__ qkv, float* __restrict__ attn)
{
    extern __shared__ float sm[];
    float* QP = sm;
    float* Ks = sm + QP_F;
    float* Vs = Ks + K_F;
    uint32_t* QPu = reinterpret_cast<uint32_t*>(QP);
    const uint32_t* Ksu = reinterpret_cast<const uint32_t*>(Ks);
    const uint32_t* Vsu = reinterpret_cast<const uint32_t*>(Vs);

    const int tid  = threadIdx.x;
    const int lane = tid & 31;
    const int warp = tid >> 5;          // 0..3
    const int g = lane >> 2;            // 0..7
    const int t = lane & 3;             // 0..3
    const int q0 = (15 - blockIdx.x) * 64;   // heavy tiles first
    const int bh = blockIdx.y;
    const int b  = bh >> 4;
    const int h  = bh & 15;

    const float* qbase = qkv + (size_t)b * S_ * 3072 + h * DH_;
    const float* kbase = qbase + D_;
    const float* vbase = qbase + 2 * D_;

    // ---- Load Q tile (64 rows; scale 1/8 = exact exponent shift) ----
    #pragma unroll
    for (int i = 0; i < 8; ++i) {
        int idx = tid + i * 128;
        int r = idx >> 4, c4 = idx & 15;
        float4 v = *reinterpret_cast<const float4*>(
            qbase + (size_t)(q0 + r) * 3072 + c4 * 4);
        v.x *= 0.125f; v.y *= 0.125f; v.z *= 0.125f; v.w *= 0.125f;
        *reinterpret_cast<float4*>(QP + r * QP_STRIDE + c4 * 4) = v;
    }
    __syncthreads();

    // ---- Q fragments (raw bits, data already tf32) ----
    const int rowA = warp * 16 + g;     // 0..63
    uint32_t qf[8][4];
    #pragma unroll
    for (int kk = 0; kk < 8; ++kk) {
        int c = kk * 8;
        qf[kk][0] = QPu[(rowA    ) * QP_STRIDE + c + t    ];
        qf[kk][1] = QPu[(rowA + 8) * QP_STRIDE + c + t    ];
        qf[kk][2] = QPu[(rowA    ) * QP_STRIDE + c + t + 4];
        qf[kk][3] = QPu[(rowA + 8) * QP_STRIDE + c + t + 4];
    }

    float of[8][4];
    #pragma unroll
    for (int nt = 0; nt < 8; ++nt)
        #pragma unroll
        for (int f = 0; f < 4; ++f) of[nt][f] = 0.0f;
    float m0 = -1e30f, m1 = -1e30f, l0 = 0.0f, l1 = 0.0f;

    const int nTiles = q0 / 64 + 1;
    for (int kt = 0; kt < nTiles; ++kt) {
        const int ks = kt * 64;
        __syncthreads();   // previous iteration's Ks/Vs/QPu reads done

        // ---- Load K,V tiles (64x64 each) ----
        #pragma unroll
        for (int i = 0; i < 8; ++i) {
            int idx = tid + i * 128;
            int r = idx >> 4, c4 = idx & 15;
            *reinterpret_cast<float4*>(Ks + r * K_STRIDE + c4 * 4) =
                *reinterpret_cast<const float4*>(
                    kbase + (size_t)(ks + r) * 3072 + c4 * 4);
            *reinterpret_cast<float4*>(Vs + r * V_STRIDE + c4 * 4) =
                *reinterpret_cast<const float4*>(
                    vbase + (size_t)(ks + r) * 3072 + c4 * 4);
        }
        __syncthreads();

        // ---- S = (Q/8) @ K^T ----
        float sv[8][4];
        #pragma unroll
        for (int nt = 0; nt < 8; ++nt) {
            sv[nt][0] = sv[nt][1] = sv[nt][2] = sv[nt][3] = 0.0f;
            #pragma unroll
            for (int kk = 0; kk < 8; ++kk) {
                uint32_t b0 = Ksu[(nt * 8 + g) * K_STRIDE + kk * 8 + t    ];
                uint32_t b1 = Ksu[(nt * 8 + g) * K_STRIDE + kk * 8 + t + 4];
                mma_tf32(sv[nt][0], sv[nt][1], sv[nt][2], sv[nt][3],
                         qf[kk][0], qf[kk][1], qf[kk][2], qf[kk][3], b0, b1);
            }
        }

        // ---- Causal mask (only the diagonal tile ks == q0) ----
        if (ks >= q0) {
            int r0 = q0 + rowA, r1 = r0 + 8;
            #pragma unroll
            for (int nt = 0; nt < 8; ++nt) {
                int c0 = ks + nt * 8 + 2 * t, c1 = c0 + 1;
                if (c0 > r0) sv[nt][0] = -1e30f;
                if (c1 > r0) sv[nt][1] = -1e30f;
                if (c0 > r1) sv[nt][2] = -1e30f;
                if (c1 > r1) sv[nt][3] = -1e30f;
            }
        }

        // ---- Online softmax ----
        float rx0 = -1e30f, rx1 = -1e30f;
        #pragma unroll
        for (int nt = 0; nt < 8; ++nt) {
            rx0 = fmaxf(rx0, fmaxf(sv[nt][0], sv[nt][1]));
            rx1 = fmaxf(rx1, fmaxf(sv[nt][2], sv[nt][3]));
        }
        rx0 = fmaxf(rx0, __shfl_xor_sync(0xffffffffu, rx0, 1));
        rx0 = fmaxf(rx0, __shfl_xor_sync(0xffffffffu, rx0, 2));
        rx1 = fmaxf(rx1, __shfl_xor_sync(0xffffffffu, rx1, 1));
        rx1 = fmaxf(rx1, __shfl_xor_sync(0xffffffffu, rx1, 2));

        float mn0 = fmaxf(m0, rx0), mn1 = fmaxf(m1, rx1);
        float corr0 = __expf(m0 - mn0), corr1 = __expf(m1 - mn1);
        m0 = mn0; m1 = mn1;

        float ps0 = 0.0f, ps1 = 0.0f;
        #pragma unroll
        for (int nt = 0; nt < 8; ++nt) {
            float p0 = __expf(sv[nt][0] - m0);
            float p1 = __expf(sv[nt][1] - m0);
            float p2 = __expf(sv[nt][2] - m1);
            float p3 = __expf(sv[nt][3] - m1);
            ps0 += p0 + p1;
            ps1 += p2 + p3;
            uint2 w0; w0.x = f2tf32(p0); w0.y = f2tf32(p1);
            uint2 w1; w1.x = f2tf32(p2); w1.y = f2tf32(p3);
            *reinterpret_cast<uint2*>(QPu + (rowA    ) * QP_STRIDE + nt * 8 + 2 * t) = w0;
            *reinterpret_cast<uint2*>(QPu + (rowA + 8) * QP_STRIDE + nt * 8 + 2 * t) = w1;
        }
        ps0 += __shfl_xor_sync(0xffffffffu, ps0, 1);
        ps0 += __shfl_xor_sync(0xffffffffu, ps0, 2);
        ps1 += __shfl_xor_sync(0xffffffffu, ps1, 1);
        ps1 += __shfl_xor_sync(0xffffffffu, ps1, 2);
        l0 = l0 * corr0 + ps0;
        l1 = l1 * corr1 + ps1;

        #pragma unroll
        for (int nt = 0; nt < 8; ++nt) {
            of[nt][0] *= corr0; of[nt][1] *= corr0;
            of[nt][2] *= corr1; of[nt][3] *= corr1;
        }
        __syncwarp();   // P rows are warp-private: order STS before LDS

        // ---- O += P @ V ----
        #pragma unroll
        for (int kk = 0; kk < 8; ++kk) {
            uint32_t a0 = QPu[(rowA    ) * QP_STRIDE + kk * 8 + t    ];
            uint32_t a1 = QPu[(rowA + 8) * QP_STRIDE + kk * 8 + t    ];
            uint32_t a2 = QPu[(rowA    ) * QP_STRIDE + kk * 8 + t + 4];
            uint32_t a3 = QPu[(rowA + 8) * QP_STRIDE + kk * 8 + t + 4];
            #pragma unroll
            for (int nt = 0; nt < 8; ++nt) {
                uint32_t b0 = Vsu[(kk * 8 + t    ) * V_STRIDE + nt * 8 + g];
                uint32_t b1 = Vsu[(kk * 8 + t + 4) * V_STRIDE + nt * 8 + g];
                mma_tf32(of[nt][0], of[nt][1], of[nt][2], of[nt][3],
                         a0, a1, a2, a3, b0, b1);
            }
        }
    }

    // ---- Normalize, round to tf32, store head-regrouped ----
    const float inv0 = 1.0f / l0;
    const float inv1 = 1.0f / l1;
    const int r0 = q0 + rowA;
    float* obase = attn + ((size_t)b * S_ + r0) * D_ + h * DH_;
    #pragma unroll
    for (int nt = 0; nt < 8; ++nt) {
        int col = nt * 8 + 2 * t;
        float2 v0, v1;
        v0.x = tf32r(of[nt][0] * inv0); v0.y = tf32r(of[nt][1] * inv0);
        v1.x = tf32r(of[nt][2] * inv1); v1.y = tf32r(of[nt][3] * inv1);
        *reinterpret_cast<float2*>(obase + col) = v0;
        *reinterpret_cast<float2*>(obase + 8 * (size_t)D_ + col) = v1;
    }
}

// ---------------------------------------------------------------------------
// Launch
// ---------------------------------------------------------------------------
extern "C" void kernel_launch(void* const* d_in, const int* in_sizes, int n_in,
                              void* d_out, int out_size)
{
    (void)in_sizes; (void)n_in; (void)out_size;
    const float* x     = (const float*)d_in[0];
    const float* W_qkv = (const float*)d_in[1];
    const float* b_qkv = (const float*)d_in[2];
    const float* W_out = (const float*)d_in[3];
    const float* b_out = (const float*)d_in[4];
    float* out = (float*)d_out;

    float *qkv, *attn, *xr, *wqkvr, *woutr;
    cudaGetSymbolAddress((void**)&qkv,   g_qkv);
    cudaGetSymbolAddress((void**)&attn,  g_attn);
    cudaGetSymbolAddress((void**)&xr,    g_x);
    cudaGetSymbolAddress((void**)&wqkvr, g_wqkv);
    cudaGetSymbolAddress((void**)&woutr, g_wout);

    cudaFuncSetAttribute(gemm_tf32_kernel<true>,
                         cudaFuncAttributeMaxDynamicSharedMemorySize, SMEM_BYTES);
    cudaFuncSetAttribute(gemm_tf32_kernel<false>,
                         cudaFuncAttributeMaxDynamicSharedMemorySize, SMEM_BYTES);
    cudaFuncSetAttribute(attention_tc_kernel,
                         cudaFuncAttributeMaxDynamicSharedMemorySize, ATT_SMEM_BYTES);

    // 0) Pre-round inputs to tf32-representable fp32
    {
        int nx = B_ * S_ * D_ / 4;
        round_tf32_kernel<<<(nx + 255) / 256, 256>>>(x, xr, nx);
        int nw = D_ * 3 * D_ / 4;
        round_tf32_kernel<<<(nw + 255) / 256, 256>>>(W_qkv, wqkvr, nw);
        int no = D_ * D_ / 4;
        round_tf32_kernel<<<(no + 255) / 256, 256>>>(W_out, woutr, no);
    }

    // 1) QKV projection -> g_qkv (tf32-rounded output)
    {
        dim3 grid(3 * D_ / 128, (B_ * S_) / 128);
        gemm_tf32_kernel<true><<<grid, 128, SMEM_BYTES>>>(xr, wqkvr, b_qkv, qkv,
                                                          B_ * S_, 3 * D_, D_);
    }

    // 2) Tensor-core causal flash attention -> g_attn (tf32-rounded)
    {
        dim3 grid(S_ / 64, B_ * H_);                // (16, 128)
        attention_tc_kernel<<<grid, 128, ATT_SMEM_BYTES>>>(qkv, attn);
    }

    // 3) Output projection -> d_out (full fp32 output)
    {
        dim3 grid(D_ / 128, (B_ * S_) / 128);
        gemm_tf32_kernel<false><<<grid, 128, SMEM_BYTES>>>(attn, woutr, b_out, out,
                                                           B_ * S_, D_, D_);
    }
}

// round 13
// speedup vs baseline: 1.0185x; 1.0185x over previous
#include <cuda_runtime.h>
#include <cstdint>

// Problem constants
#define B_  8
#define S_  1024
#define D_  1024
#define H_  16
#define DH_ 64

// Scratch buffers (allocation-free rule: __device__ globals)
__device__ float g_qkv[(size_t)B_ * S_ * 3 * D_];   // [B, S, 3D] tf32-rounded
__device__ float g_attn[(size_t)B_ * S_ * D_];      // [B, S, D]  tf32-rounded
__device__ float g_x[(size_t)B_ * S_ * D_];         // tf32-rounded copy of x
__device__ float g_wqkv[(size_t)D_ * 3 * D_];       // tf32-rounded W_qkv
__device__ float g_wout[(size_t)D_ * D_];           // tf32-rounded W_out

// ---------------------------------------------------------------------------
// TF32 helpers
// ---------------------------------------------------------------------------
__device__ __forceinline__ uint32_t f2tf32(float f) {
    uint32_t r;
    asm("cvt.rna.tf32.f32 %0, %1;" : "=r"(r) : "f"(f));
    return r;
}
__device__ __forceinline__ float tf32r(float f) {
    return __uint_as_float(f2tf32(f));
}

__device__ __forceinline__ void mma_tf32(
    float& d0, float& d1, float& d2, float& d3,
    uint32_t a0, uint32_t a1, uint32_t a2, uint32_t a3,
    uint32_t b0, uint32_t b1)
{
    asm volatile(
        "mma.sync.aligned.m16n8k8.row.col.f32.tf32.tf32.f32 "
        "{%0,%1,%2,%3}, {%4,%5,%6,%7}, {%8,%9}, {%0,%1,%2,%3};"
        : "+f"(d0), "+f"(d1), "+f"(d2), "+f"(d3)
        : "r"(a0), "r"(a1), "r"(a2), "r"(a3), "r"(b0), "r"(b1));
}

__device__ __forceinline__ void cp_async16(uint32_t s, const void* g) {
    asm volatile("cp.async.cg.shared.global [%0], [%1], 16;" :: "r"(s), "l"(g));
}
__device__ __forceinline__ uint32_t smem_u32(const void* p) {
    return (uint32_t)__cvta_generic_to_shared(p);
}

// ---------------------------------------------------------------------------
// Elementwise tf32 pre-round (float4 grid-stride)
// ---------------------------------------------------------------------------
__global__ void round_tf32_kernel(const float* __restrict__ in,
                                  float* __restrict__ out, int n4)
{
    int i = blockIdx.x * blockDim.x + threadIdx.x;
    if (i < n4) {
        float4 v = reinterpret_cast<const float4*>(in)[i];
        v.x = tf32r(v.x); v.y = tf32r(v.y);
        v.z = tf32r(v.z); v.w = tf32r(v.w);
        reinterpret_cast<float4*>(out)[i] = v;
    }
}

// ---------------------------------------------------------------------------
// TF32 GEMM (unchanged from R8 best): block 128x128, 4 warps (2x2), warp
// tile 64x64, BK=32, 3-stage cp.async pipeline + reg double-buffered frags.
// ---------------------------------------------------------------------------
#define AS_STRIDE 36
#define BS_STRIDE 136
#define A_TILE_F (128 * AS_STRIDE)
#define B_TILE_F (32 * BS_STRIDE)
#define BUF_F    (A_TILE_F + B_TILE_F)
#define SMEM_BYTES (3 * BUF_F * 4)

template<bool ROUND_OUT>
__global__ __launch_bounds__(128, 2) void gemm_tf32_kernel(
    const float* __restrict__ A, const float* __restrict__ W,
    const float* __restrict__ bias, float* __restrict__ C,
    int M, int N, int K)
{
    extern __shared__ float sm[];

    const int tid  = threadIdx.x;
    const int lane = tid & 31;
    const int warp = tid >> 5;
    const int wm   = warp & 1;
    const int wn   = warp >> 1;
    const int mBase = blockIdx.y * 128;
    const int nBase = blockIdx.x * 128;
    const int g  = lane >> 2;
    const int t  = lane & 3;

    float acc[4][8][4];
    #pragma unroll
    for (int mt = 0; mt < 4; ++mt)
        #pragma unroll
        for (int nt = 0; nt < 8; ++nt)
            #pragma unroll
            for (int f = 0; f < 4; ++f) acc[mt][nt][f] = 0.0f;

    auto loadTile = [&](int buf, int k0) {
        float* As = sm + buf * BUF_F;
        float* Bs = As + A_TILE_F;
        #pragma unroll
        for (int j = 0; j < 8; ++j) {
            int idx = tid + j * 128;
            int r = idx >> 3, c4 = idx & 7;
            cp_async16(smem_u32(As + r * AS_STRIDE + c4 * 4),
                       &A[(size_t)(mBase + r) * K + k0 + c4 * 4]);
        }
        #pragma unroll
        for (int j = 0; j < 8; ++j) {
            int idx = tid + j * 128;
            int r = idx >> 5, c4 = idx & 31;
            cp_async16(smem_u32(Bs + r * BS_STRIDE + c4 * 4),
                       &W[(size_t)(k0 + r) * N + nBase + c4 * 4]);
        }
        asm volatile("cp.async.commit_group;");
    };

    uint32_t af[2][4][4];
    uint32_t bf[2][8][2];

    const int aRow = wm * 64;
    const int bCol = wn * 64;

    auto loadFragsA = [&](int pb, const uint32_t* As, int kc) {
        #pragma unroll
        for (int mt = 0; mt < 4; ++mt) {
            int r = aRow + mt * 16 + g;
            af[pb][mt][0] = As[(r    ) * AS_STRIDE + kc + t    ];
            af[pb][mt][1] = As[(r + 8) * AS_STRIDE + kc + t    ];
            af[pb][mt][2] = As[(r    ) * AS_STRIDE + kc + t + 4];
            af[pb][mt][3] = As[(r + 8) * AS_STRIDE + kc + t + 4];
        }
    };
    auto loadFragsB = [&](int pb, const uint32_t* Bs, int kc) {
        #pragma unroll
        for (int nt = 0; nt < 8; ++nt) {
            int n = bCol + nt * 8 + g;
            bf[pb][nt][0] = Bs[(kc + t    ) * BS_STRIDE + n];
            bf[pb][nt][1] = Bs[(kc + t + 4) * BS_STRIDE + n];
        }
    };

    const int nIter = K / 32;
    loadTile(0, 0);
    loadTile(1, 32);

    for (int it = 0; it < nIter; ++it) {
        if (it + 1 < nIter) {
            asm volatile("cp.async.wait_group 1;");
        } else {
            asm volatile("cp.async.wait_group 0;");
        }
        __syncthreads();

        if (it + 2 < nIter)
            loadTile((it + 2) % 3, (it + 2) * 32);

        const uint32_t* As = reinterpret_cast<const uint32_t*>(sm + (it % 3) * BUF_F);
        const uint32_t* Bs = As + A_TILE_F;

        loadFragsA(0, As, 0);
        loadFragsB(0, Bs, 0);

        #pragma unroll
        for (int kk = 0; kk < 4; ++kk) {
            const int cur = kk & 1;
            const int nxt = cur ^ 1;
            if (kk < 3) {
                loadFragsA(nxt, As, (kk + 1) * 8);
                loadFragsB(nxt, Bs, (kk + 1) * 8);
            }
            #pragma unroll
            for (int mt = 0; mt < 4; ++mt)
                #pragma unroll
                for (int nt = 0; nt < 8; ++nt)
                    mma_tf32(acc[mt][nt][0], acc[mt][nt][1],
                             acc[mt][nt][2], acc[mt][nt][3],
                             af[cur][mt][0], af[cur][mt][1],
                             af[cur][mt][2], af[cur][mt][3],
                             bf[cur][nt][0], bf[cur][nt][1]);
        }
    }

    #pragma unroll
    for (int mt = 0; mt < 4; ++mt) {
        int r0 = mBase + wm * 64 + mt * 16 + g;
        int r1 = r0 + 8;
        #pragma unroll
        for (int nt = 0; nt < 8; ++nt) {
            int col = nBase + wn * 64 + nt * 8 + t * 2;
            float2 bv = *reinterpret_cast<const float2*>(&bias[col]);
            float2 v0, v1;
            v0.x = acc[mt][nt][0] + bv.x;
            v0.y = acc[mt][nt][1] + bv.y;
            v1.x = acc[mt][nt][2] + bv.x;
            v1.y = acc[mt][nt][3] + bv.y;
            if (ROUND_OUT) {
                v0.x = tf32r(v0.x); v0.y = tf32r(v0.y);
                v1.x = tf32r(v1.x); v1.y = tf32r(v1.y);
            }
            *reinterpret_cast<float2*>(&C[(size_t)r0 * N + col]) = v0;
            *reinterpret_cast<float2*>(&C[(size_t)r1 * N + col]) = v1;
        }
    }
}

// ---------------------------------------------------------------------------
// Tensor-core FlashAttention v3 (tf32, causal): 128-row q-tile, 256 threads,
// 8 warps (16 rows each) — R5 structure — plus cp.async DOUBLE-BUFFERED K/V
// tiles so the global load of tile kt+1 overlaps compute of tile kt.
// smem: QP(128x68) + 2 stages of [K(64x68) + V(64x72)] = 104 KB, 2 CTAs/SM.
// grid = (8, B*H), q0 = (7-bx)*128 (heavy tiles first).
// ---------------------------------------------------------------------------
#define QP_STRIDE 68
#define K_STRIDE  68
#define V_STRIDE  72
#define QP_F   (128 * QP_STRIDE)        // 8704 floats
#define KV_K_F (64 * K_STRIDE)          // 4352 floats
#define KV_V_F (64 * V_STRIDE)          // 4608 floats
#define STAGE_F (KV_K_F + KV_V_F)       // 8960 floats
#define ATT_SMEM_BYTES ((QP_F + 2 * STAGE_F) * 4)   // 106496 B

__global__ __launch_bounds__(256, 2) void attention_tc_kernel(
    const float* __restrict__ qkv, float* __restrict__ attn)
{
    extern __shared__ float sm[];
    float* QP = sm;
    uint32_t* QPu = reinterpret_cast<uint32_t*>(QP);

    const int tid  = threadIdx.x;
    const int lane = tid & 31;
    const int warp = tid >> 5;          // 0..7
    const int g = lane >> 2;            // 0..7
    const int t = lane & 3;             // 0..3
    const int q0 = (7 - blockIdx.x) * 128;   // heavy tiles first
    const int bh = blockIdx.y;
    const int b  = bh >> 4;
    const int h  = bh & 15;

    const float* qbase = qkv + (size_t)b * S_ * 3072 + h * DH_;
    const float* kbase = qbase + D_;
    const float* vbase = qbase + 2 * D_;

    // ---- cp.async stage loader: K,V tile of 64 rows into stage buf ----
    auto load_stage = [&](int buf, int ks) {
        float* Ks = sm + QP_F + buf * STAGE_F;
        float* Vs = Ks + KV_K_F;
        #pragma unroll
        for (int i = 0; i < 4; ++i) {
            int idx = tid + i * 256;
            int r = idx >> 4, c4 = idx & 15;
            cp_async16(smem_u32(Ks + r * K_STRIDE + c4 * 4),
                       kbase + (size_t)(ks + r) * 3072 + c4 * 4);
            cp_async16(smem_u32(Vs + r * V_STRIDE + c4 * 4),
                       vbase + (size_t)(ks + r) * 3072 + c4 * 4);
        }
        asm volatile("cp.async.commit_group;");
    };

    const int nTiles = q0 / 64 + 2;
    load_stage(0, 0);                    // prefetch tile 0 first (deepest latency)

    // ---- Load Q tile (scale 1/8 = exact exponent shift) ----
    #pragma unroll
    for (int i = 0; i < 8; ++i) {
        int idx = tid + i * 256;
        int r = idx >> 4, c4 = idx & 15;
        float4 v = *reinterpret_cast<const float4*>(
            qbase + (size_t)(q0 + r) * 3072 + c4 * 4);
        v.x *= 0.125f; v.y *= 0.125f; v.z *= 0.125f; v.w *= 0.125f;
        *reinterpret_cast<float4*>(QP + r * QP_STRIDE + c4 * 4) = v;
    }
    __syncthreads();

    // ---- Q fragments (raw bits, data already tf32) ----
    const int rowA = warp * 16 + g;
    uint32_t qf[8][4];
    #pragma unroll
    for (int kk = 0; kk < 8; ++kk) {
        int c = kk * 8;
        qf[kk][0] = QPu[(rowA    ) * QP_STRIDE + c + t    ];
        qf[kk][1] = QPu[(rowA + 8) * QP_STRIDE + c + t    ];
        qf[kk][2] = QPu[(rowA    ) * QP_STRIDE + c + t + 4];
        qf[kk][3] = QPu[(rowA + 8) * QP_STRIDE + c + t + 4];
    }

    float of[8][4];
    #pragma unroll
    for (int nt = 0; nt < 8; ++nt)
        #pragma unroll
        for (int f = 0; f < 4; ++f) of[nt][f] = 0.0f;
    float m0 = -1e30f, m1 = -1e30f, l0 = 0.0f, l1 = 0.0f;

    for (int kt = 0; kt < nTiles; ++kt) {
        const int ks = kt * 64;
        const int buf = kt & 1;

        // A: all threads done with compute of kt-1 (protects buffer (kt+1)&1,
        //    last written for tile kt-1) and with QPu reads of kt-1.
        __syncthreads();
        if (kt + 1 < nTiles)
            load_stage(buf ^ 1, ks + 64);

        // Tile kt's cp.async group done (FIFO; 1 newer group may be pending).
        if (kt + 1 < nTiles) asm volatile("cp.async.wait_group 1;");
        else                 asm volatile("cp.async.wait_group 0;");
        __syncthreads();   // B: all threads' copies for tile kt visible

        const uint32_t* Ksu = reinterpret_cast<const uint32_t*>(sm + QP_F + buf * STAGE_F);
        const uint32_t* Vsu = Ksu + KV_K_F;

        // ---- S = (Q/8) @ K^T ----
        float sv[8][4];
        #pragma unroll
        for (int nt = 0; nt < 8; ++nt) {
            sv[nt][0] = sv[nt][1] = sv[nt][2] = sv[nt][3] = 0.0f;
            #pragma unroll
            for (int kk = 0; kk < 8; ++kk) {
                uint32_t b0 = Ksu[(nt * 8 + g) * K_STRIDE + kk * 8 + t    ];
                uint32_t b1 = Ksu[(nt * 8 + g) * K_STRIDE + kk * 8 + t + 4];
                mma_tf32(sv[nt][0], sv[nt][1], sv[nt][2], sv[nt][3],
                         qf[kk][0], qf[kk][1], qf[kk][2], qf[kk][3], b0, b1);
            }
        }

        // ---- Causal mask (only diagonal tiles) ----
        if (ks >= q0) {
            int r0 = q0 + rowA, r1 = r0 + 8;
            #pragma unroll
            for (int nt = 0; nt < 8; ++nt) {
                int c0 = ks + nt * 8 + 2 * t, c1 = c0 + 1;
                if (c0 > r0) sv[nt][0] = -1e30f;
                if (c1 > r0) sv[nt][1] = -1e30f;
                if (c0 > r1) sv[nt][2] = -1e30f;
                if (c1 > r1) sv[nt][3] = -1e30f;
            }
        }

        // ---- Online softmax ----
        float rx0 = -1e30f, rx1 = -1e30f;
        #pragma unroll
        for (int nt = 0; nt < 8; ++nt) {
            rx0 = fmaxf(rx0, fmaxf(sv[nt][0], sv[nt][1]));
            rx1 = fmaxf(rx1, fmaxf(sv[nt][2], sv[nt][3]));
        }
        rx0 = fmaxf(rx0, __shfl_xor_sync(0xffffffffu, rx0, 1));
        rx0 = fmaxf(rx0, __shfl_xor_sync(0xffffffffu, rx0, 2));
        rx1 = fmaxf(rx1, __shfl_xor_sync(0xffffffffu, rx1, 1));
        rx1 = fmaxf(rx1, __shfl_xor_sync(0xffffffffu, rx1, 2));

        float mn0 = fmaxf(m0, rx0), mn1 = fmaxf(m1, rx1);
        float corr0 = __expf(m0 - mn0), corr1 = __expf(m1 - mn1);
        m0 = mn0; m1 = mn1;

        float ps0 = 0.0f, ps1 = 0.0f;
        #pragma unroll
        for (int nt = 0; nt < 8; ++nt) {
            float p0 = __expf(sv[nt][0] - m0);
            float p1 = __expf(sv[nt][1] - m0);
            float p2 = __expf(sv[nt][2] - m1);
            float p3 = __expf(sv[nt][3] - m1);
            ps0 += p0 + p1;
            ps1 += p2 + p3;
            uint2 w0; w0.x = f2tf32(p0); w0.y = f2tf32(p1);
            uint2 w1; w1.x = f2tf32(p2); w1.y = f2tf32(p3);
            *reinterpret_cast<uint2*>(QPu + (rowA    ) * QP_STRIDE + nt * 8 + 2 * t) = w0;
            *reinterpret_cast<uint2*>(QPu + (rowA + 8) * QP_STRIDE + nt * 8 + 2 * t) = w1;
        }
        ps0 += __shfl_xor_sync(0xffffffffu, ps0, 1);
        ps0 += __shfl_xor_sync(0xffffffffu, ps0, 2);
        ps1 += __shfl_xor_sync(0xffffffffu, ps1, 1);
        ps1 += __shfl_xor_sync(0xffffffffu, ps1, 2);
        l0 = l0 * corr0 + ps0;
        l1 = l1 * corr1 + ps1;

        #pragma unroll
        for (int nt = 0; nt < 8; ++nt) {
            of[nt][0] *= corr0; of[nt][1] *= corr0;
            of[nt][2] *= corr1; of[nt][3] *= corr1;
        }
        __syncwarp();   // P rows are warp-private: order STS before LDS

        // ---- O += P @ V ----
        #pragma unroll
        for (int kk = 0; kk < 8; ++kk) {
            uint32_t a0 = QPu[(rowA    ) * QP_STRIDE + kk * 8 + t    ];
            uint32_t a1 = QPu[(rowA + 8) * QP_STRIDE + kk * 8 + t    ];
            uint32_t a2 = QPu[(rowA    ) * QP_STRIDE + kk * 8 + t + 4];
            uint32_t a3 = QPu[(rowA + 8) * QP_STRIDE + kk * 8 + t + 4];
            #pragma unroll
            for (int nt = 0; nt < 8; ++nt) {
                uint32_t b0 = Vsu[(kk * 8 + t    ) * V_STRIDE + nt * 8 + g];
                uint32_t b1 = Vsu[(kk * 8 + t + 4) * V_STRIDE + nt * 8 + g];
                mma_tf32(of[nt][0], of[nt][1], of[nt][2], of[nt][3],
                         a0, a1, a2, a3, b0, b1);
            }
        }
    }

    // ---- Normalize, round to tf32, store head-regrouped ----
    const float inv0 = 1.0f / l0;
    const float inv1 = 1.0f / l1;
    const int r0 = q0 + rowA;
    float* obase = attn + ((size_t)b * S_ + r0) * D_ + h * DH_;
    #pragma unroll
    for (int nt = 0; nt < 8; ++nt) {
        int col = nt * 8 + 2 * t;
        float2 v0, v1;
        v0.x = tf32r(of[nt][0] * inv0); v0.y = tf32r(of[nt][1] * inv0);
        v1.x = tf32r(of[nt][2] * inv1); v1.y = tf32r(of[nt][3] * inv1);
        *reinterpret_cast<float2*>(obase + col) = v0;
        *reinterpret_cast<float2*>(obase + 8 * (size_t)D_ + col) = v1;
    }
}

// ---------------------------------------------------------------------------
// Launch
// ---------------------------------------------------------------------------
extern "C" void kernel_launch(void* const* d_in, const int* in_sizes, int n_in,
                              void* d_out, int out_size)
{
    (void)in_sizes; (void)n_in; (void)out_size;
    const float* x     = (const float*)d_in[0];
    const float* W_qkv = (const float*)d_in[1];
    const float* b_qkv = (const float*)d_in[2];
    const float* W_out = (const float*)d_in[3];
    const float* b_out = (const float*)d_in[4];
    float* out = (float*)d_out;

    float *qkv, *attn, *xr, *wqkvr, *woutr;
    cudaGetSymbolAddress((void**)&qkv,   g_qkv);
    cudaGetSymbolAddress((void**)&attn,  g_attn);
    cudaGetSymbolAddress((void**)&xr,    g_x);
    cudaGetSymbolAddress((void**)&wqkvr, g_wqkv);
    cudaGetSymbolAddress((void**)&woutr, g_wout);

    cudaFuncSetAttribute(gemm_tf32_kernel<true>,
                         cudaFuncAttributeMaxDynamicSharedMemorySize, SMEM_BYTES);
    cudaFuncSetAttribute(gemm_tf32_kernel<false>,
                         cudaFuncAttributeMaxDynamicSharedMemorySize, SMEM_BYTES);
    cudaFuncSetAttribute(attention_tc_kernel,
                         cudaFuncAttributeMaxDynamicSharedMemorySize, ATT_SMEM_BYTES);

    // 0) Pre-round inputs to tf32-representable fp32
    {
        int nx = B_ * S_ * D_ / 4;
        round_tf32_kernel<<<(nx + 255) / 256, 256>>>(x, xr, nx);
        int nw = D_ * 3 * D_ / 4;
        round_tf32_kernel<<<(nw + 255) / 256, 256>>>(W_qkv, wqkvr, nw);
        int no = D_ * D_ / 4;
        round_tf32_kernel<<<(no + 255) / 256, 256>>>(W_out, woutr, no);
    }

    // 1) QKV projection -> g_qkv (tf32-rounded output)
    {
        dim3 grid(3 * D_ / 128, (B_ * S_) / 128);
        gemm_tf32_kernel<true><<<grid, 128, SMEM_BYTES>>>(xr, wqkvr, b_qkv, qkv,
                                                          B_ * S_, 3 * D_, D_);
    }

    // 2) Tensor-core causal flash attention -> g_attn (tf32-rounded)
    {
        dim3 grid(S_ / 128, B_ * H_);               // (8, 128)
        attention_tc_kernel<<<grid, 256, ATT_SMEM_BYTES>>>(qkv, attn);
    }

    // 3) Output projection -> d_out (full fp32 output)
    {
        dim3 grid(D_ / 128, (B_ * S_) / 128);
        gemm_tf32_kernel<false><<<grid, 128, SMEM_BYTES>>>(attn, woutr, b_out, out,
                                                           B_ * S_, D_, D_);
    }
}